// round 4
// baseline (speedup 1.0000x reference)
#include <cuda_runtime.h>
#include <cstdint>
#include <math.h>

#define IN_DIM 128
#define HID    32
#define NCLS   30
#define CP     32            // padded row width (128B rows)
#define NMAX   100000
#define EMAX   3200000
#define G2MAX  1024          // gather2 grid size (fixed)
#define PARTM  32768
#define REG_C  0.01

// ---------------- static scratch ----------------
__device__ float  d_bufA[NMAX * CP];    // g1 -> FX(padded)
__device__ float  d_bufB[NMAX * CP];    // h1 (post-relu)
__device__ float  d_bufC[NMAX * CP];    // g2
__device__ int    d_cnt [NMAX + 1];     // in-degree counts
__device__ int    d_cur [NMAX];         // scan temp, then fill cursor
__device__ int    d_rp  [NMAX + 1];     // CSR row pointers
__device__ int    d_src32[EMAX];
__device__ int    d_dst32[EMAX];
__device__ int    d_csr [EMAX];         // src per in-edge, grouped by dst
__device__ float  d_dinv[NMAX];
__device__ int    d_blocksum[1024];
__device__ float  d_partialS[32 * G2MAX];
__device__ float  d_partialM[PARTM];
__device__ int    d_is64;

// ---------------- dtype detector (int64 vs int32 edge_index) -------------
__global__ void detect_k(const unsigned int* __restrict__ w) {
    int t = threadIdx.x;                       // 64 threads
    unsigned int v = w[2 * t + 1];             // hi-words if int64
    unsigned int any = __ballot_sync(0xffffffffu, v != 0);
    if (t == 0) d_is64 = (any == 0) ? 1 : 0;
}

// ---------------- init ----------------
__global__ void init_k(int N) {
    int i = blockIdx.x * blockDim.x + threadIdx.x;
    if (i <= N) d_cnt[i] = 0;
}

// ---------------- count + int32 conversion --------------------------------
__global__ void count_convert(const void* __restrict__ ei, int E) {
    int e = blockIdx.x * blockDim.x + threadIdx.x;
    if (e >= E) return;
    int s, d;
    if (d_is64) {
        const long long* p = (const long long*)ei;
        s = (int)p[e]; d = (int)p[(size_t)E + e];
    } else {
        const int* p = (const int*)ei;
        s = p[e]; d = p[(size_t)E + e];
    }
    d_src32[e] = s; d_dst32[e] = d;
    atomicAdd(&d_cnt[d], 1);
}

__global__ void dinv_k(int N) {
    int i = blockIdx.x * blockDim.x + threadIdx.x;
    if (i < N) d_dinv[i] = rsqrtf((float)(d_cnt[i] + 1));   // +1 self loop
}

// ---------------- 3-phase exclusive scan ----------------------------------
__global__ void scan1(int N) {
    __shared__ int sh[1024];
    int gid = blockIdx.x * 1024 + threadIdx.x;
    int v = (gid < N) ? d_cnt[gid] : 0;
    sh[threadIdx.x] = v; __syncthreads();
    for (int off = 1; off < 1024; off <<= 1) {
        int t = (threadIdx.x >= off) ? sh[threadIdx.x - off] : 0;
        __syncthreads();
        sh[threadIdx.x] += t;
        __syncthreads();
    }
    int incl = sh[threadIdx.x];
    if (gid < N) d_cur[gid] = incl - v;        // block-local exclusive
    if (threadIdx.x == 1023) d_blocksum[blockIdx.x] = incl;
}

__global__ void scan2(int nb) {
    __shared__ int sh[1024];
    int v = (threadIdx.x < nb) ? d_blocksum[threadIdx.x] : 0;
    sh[threadIdx.x] = v; __syncthreads();
    for (int off = 1; off < 1024; off <<= 1) {
        int t = (threadIdx.x >= off) ? sh[threadIdx.x - off] : 0;
        __syncthreads();
        sh[threadIdx.x] += t;
        __syncthreads();
    }
    if (threadIdx.x < nb) d_blocksum[threadIdx.x] = sh[threadIdx.x] - v;
}

__global__ void scan3(int N, int E) {
    int gid = blockIdx.x * 1024 + threadIdx.x;
    if (gid < N) {
        int rp = d_cur[gid] + d_blocksum[blockIdx.x];
        d_rp[gid] = rp;
        d_cur[gid] = rp;                        // cursor init
    }
    if (gid == 0) d_rp[N] = E;
}

// ---------------- CSR fill -------------------------------------------------
__global__ void fill_k(int E) {
    int e = blockIdx.x * blockDim.x + threadIdx.x;
    if (e >= E) return;
    int d = d_dst32[e];
    int pos = atomicAdd(&d_cur[d], 1);
    d_csr[pos] = d_src32[e];
}

// ---------------- GEMM1: g1 = (x @ W1) * dinv -> bufA ----------------------
__global__ void gemm1(const float* __restrict__ x, const float* __restrict__ W1, int N) {
    __shared__ float Ws[IN_DIM * HID];
    for (int i = threadIdx.x; i < IN_DIM * HID; i += blockDim.x) Ws[i] = W1[i];
    __syncthreads();
    int r = blockIdx.x * blockDim.x + threadIdx.x;
    if (r >= N) return;

    float acc[HID];
#pragma unroll
    for (int c = 0; c < HID; c++) acc[c] = 0.f;

    const float4* x4 = reinterpret_cast<const float4*>(x + (size_t)r * IN_DIM);
#pragma unroll 4
    for (int k4 = 0; k4 < IN_DIM / 4; k4++) {
        float4 xv = x4[k4];
        int k = k4 * 4;
#pragma unroll
        for (int c = 0; c < HID; c++) {
            acc[c] += xv.x * Ws[(k + 0) * HID + c]
                    + xv.y * Ws[(k + 1) * HID + c]
                    + xv.z * Ws[(k + 2) * HID + c]
                    + xv.w * Ws[(k + 3) * HID + c];
        }
    }
    float s = d_dinv[r];
    float* out = d_bufA + (size_t)r * CP;
#pragma unroll
    for (int c = 0; c < HID; c++) out[c] = acc[c] * s;
}

// ---------------- gather layer1: h1 = relu(dinv*(sum + self) + b1) --------
__global__ void gather1(const float* __restrict__ b1, int N) {
    int tid  = threadIdx.x;
    int lane = tid & 31;
    int warp = (blockIdx.x * blockDim.x + tid) >> 5;
    int nwarps = (gridDim.x * blockDim.x) >> 5;
    float bv = b1[lane];

    for (int v = warp; v < N; v += nwarps) {
        int e = d_rp[v], end = d_rp[v + 1];
        float acc = 0.f;
        for (; e + 4 <= end; e += 4) {
            int s0 = d_csr[e], s1 = d_csr[e + 1], s2 = d_csr[e + 2], s3 = d_csr[e + 3];
            float a0 = d_bufA[(size_t)s0 * CP + lane];
            float a1 = d_bufA[(size_t)s1 * CP + lane];
            float a2 = d_bufA[(size_t)s2 * CP + lane];
            float a3 = d_bufA[(size_t)s3 * CP + lane];
            acc += (a0 + a1) + (a2 + a3);
        }
        for (; e < end; e++) {
            int s = d_csr[e];
            acc += d_bufA[(size_t)s * CP + lane];
        }
        float h = d_dinv[v] * (acc + d_bufA[(size_t)v * CP + lane]) + bv;
        d_bufB[(size_t)v * CP + lane] = fmaxf(h, 0.f);
    }
}

// ---------------- GEMM2: g2 = (h1 @ W2) * dinv -> bufC (padded) ------------
__global__ void gemm2(const float* __restrict__ W2, int N) {
    __shared__ float Ws[HID * CP];
    for (int i = threadIdx.x; i < HID * CP; i += blockDim.x) {
        int k = i / CP, c = i % CP;
        Ws[i] = (c < NCLS) ? W2[k * NCLS + c] : 0.f;
    }
    __syncthreads();
    int r = blockIdx.x * blockDim.x + threadIdx.x;
    if (r >= N) return;

    float acc[CP];
#pragma unroll
    for (int c = 0; c < CP; c++) acc[c] = 0.f;

    const float4* h4 = reinterpret_cast<const float4*>(d_bufB + (size_t)r * CP);
#pragma unroll
    for (int k4 = 0; k4 < HID / 4; k4++) {
        float4 hv = h4[k4];
        int k = k4 * 4;
#pragma unroll
        for (int c = 0; c < CP; c++) {
            acc[c] += hv.x * Ws[(k + 0) * CP + c]
                    + hv.y * Ws[(k + 1) * CP + c]
                    + hv.z * Ws[(k + 2) * CP + c]
                    + hv.w * Ws[(k + 3) * CP + c];
        }
    }
    float s = d_dinv[r];
    float* out = d_bufC + (size_t)r * CP;
#pragma unroll
    for (int c = 0; c < CP; c++) out[c] = acc[c] * s;
}

// ---------------- gather layer2 + softmax + FX + NFX column partials ------
__global__ void gather2(const float* __restrict__ b2, float* __restrict__ fx_out, int N) {
    __shared__ float Ss[32];
    int tid  = threadIdx.x;
    int lane = tid & 31;
    if (tid < 32) Ss[tid] = 0.f;
    __syncthreads();

    int warp = (blockIdx.x * blockDim.x + tid) >> 5;
    int nwarps = (gridDim.x * blockDim.x) >> 5;
    float bv = (lane < NCLS) ? b2[lane] : 0.f;
    float ls = 0.f;

    for (int v = warp; v < N; v += nwarps) {
        int e = d_rp[v], end = d_rp[v + 1];
        float acc = 0.f;
        for (; e + 4 <= end; e += 4) {
            int s0 = d_csr[e], s1 = d_csr[e + 1], s2 = d_csr[e + 2], s3 = d_csr[e + 3];
            float a0 = d_bufC[(size_t)s0 * CP + lane];
            float a1 = d_bufC[(size_t)s1 * CP + lane];
            float a2 = d_bufC[(size_t)s2 * CP + lane];
            float a3 = d_bufC[(size_t)s3 * CP + lane];
            acc += (a0 + a1) + (a2 + a3);
        }
        for (; e < end; e++) {
            int s = d_csr[e];
            acc += d_bufC[(size_t)s * CP + lane];
        }
        float logit = d_dinv[v] * (acc + d_bufC[(size_t)v * CP + lane]) + bv;
        if (lane >= NCLS) logit = -1e30f;

        float mx = logit;
#pragma unroll
        for (int o = 16; o; o >>= 1) mx = fmaxf(mx, __shfl_xor_sync(0xffffffffu, mx, o));
        float ex = expf(logit - mx);
        float sum = ex;
#pragma unroll
        for (int o = 16; o; o >>= 1) sum += __shfl_xor_sync(0xffffffffu, sum, o);
        float fx = ex / sum;

        d_bufA[(size_t)v * CP + lane] = fx;                        // padded (30,31 = 0)
        if (lane < NCLS) {
            fx_out[(size_t)v * NCLS + lane] = fx;
            ls += log1pf(-fx * fx);
        }
    }
    atomicAdd(&Ss[lane], ls);
    __syncthreads();
    if (tid < NCLS) d_partialS[tid * gridDim.x + blockIdx.x] = Ss[tid];
}

// ---------------- FF + MSE partials ---------------------------------------
__global__ void ff_k(const float* __restrict__ ep, int E) {
    __shared__ float sAcc;
    int tid = threadIdx.x;
    if (tid == 0) sAcc = 0.f;
    __syncthreads();

    int idx = blockIdx.x * blockDim.x + tid;
    int e = idx >> 3, c = idx & 7;
    float partial = 0.f;
    bool valid = (e < E);
    if (valid) {
        int s = d_src32[e];
        int d = d_dst32[e];
        float4 a = *reinterpret_cast<const float4*>(d_bufA + (size_t)s * CP + c * 4);
        float4 b = *reinterpret_cast<const float4*>(d_bufA + (size_t)d * CP + c * 4);
        partial = a.x * b.x + a.y * b.y + a.z * b.z + a.w * b.w;
    }
    partial += __shfl_down_sync(0xffffffffu, partial, 4);
    partial += __shfl_down_sync(0xffffffffu, partial, 2);
    partial += __shfl_down_sync(0xffffffffu, partial, 1);

    float d2 = 0.f;
    if (valid && c == 0) {
        float diff = partial - ep[e];
        d2 = diff * diff;
    }
    d2 += __shfl_down_sync(0xffffffffu, d2, 16);
    d2 += __shfl_down_sync(0xffffffffu, d2, 8);
    if ((tid & 31) == 0) atomicAdd(&sAcc, d2);
    __syncthreads();
    if (tid == 0) d_partialM[blockIdx.x] = sAcc;
}

// ---------------- finalize loss -------------------------------------------
__global__ void fin_k(float* __restrict__ out, int N, int E, int out_size, int nb_m) {
    __shared__ double sS[32];
    __shared__ double red[32];
    int tid = threadIdx.x, w = tid >> 5, lane = tid & 31;

    if (w < NCLS) {
        float s = 0.f;
        for (int k = lane; k < G2MAX; k += 32) s += d_partialS[w * G2MAX + k];
#pragma unroll
        for (int o = 16; o; o >>= 1) s += __shfl_down_sync(0xffffffffu, s, o);
        if (lane == 0) sS[w] = (double)s;
    }

    double m = 0.0;
    for (int k = tid; k < nb_m; k += 1024) m += (double)d_partialM[k];
#pragma unroll
    for (int o = 16; o; o >>= 1) m += __shfl_down_sync(0xffffffffu, m, o);
    if (lane == 0) red[w] = m;
    __syncthreads();

    if (tid == 0) {
        double mm = 0.0;
        for (int i = 0; i < 32; i++) mm += red[i];
        double preg = 0.0;
        for (int c = 0; c < NCLS; c++)
            preg -= log(1.0001 - exp(sS[c]));
        double loss = mm / (double)E + REG_C * preg;
        if (out_size > N * NCLS) out[(size_t)N * NCLS] = (float)loss;
    }
}

// ---------------- launch ---------------------------------------------------
extern "C" void kernel_launch(void* const* d_in, const int* in_sizes, int n_in,
                              void* d_out, int out_size) {
    const float* x   = (const float*)d_in[0];
    const void*  ei  = d_in[1];
    const float* ep  = (const float*)d_in[2];
    const float* W1  = (const float*)d_in[3];
    const float* b1  = (const float*)d_in[4];
    const float* W2  = (const float*)d_in[5];
    const float* b2  = (const float*)d_in[6];
    float* out = (float*)d_out;

    int N = in_sizes[0] / IN_DIM;    // 100000
    int E = in_sizes[2];             // 3200000
    int nb_scan = (N + 1023) / 1024;
    int nb_ff   = ((size_t)E * 8 + 1023) / 1024;

    const int T = 256;
    detect_k     <<<1, 64>>>((const unsigned int*)ei);
    init_k       <<<(N + 1 + T - 1) / T, T>>>(N);
    count_convert<<<(E + T - 1) / T, T>>>(ei, E);
    dinv_k       <<<(N + T - 1) / T, T>>>(N);
    scan1        <<<nb_scan, 1024>>>(N);
    scan2        <<<1, 1024>>>(nb_scan);
    scan3        <<<nb_scan, 1024>>>(N, E);
    fill_k       <<<(E + T - 1) / T, T>>>(E);

    gemm1        <<<(N + 127) / 128, 128>>>(x, W1, N);
    gather1      <<<2048, 256>>>(b1, N);
    gemm2        <<<(N + 127) / 128, 128>>>(W2, N);
    gather2      <<<G2MAX, 256>>>(b2, out, N);

    ff_k         <<<nb_ff, 1024>>>(ep, E);
    fin_k        <<<1, 1024>>>(out, N, E, out_size, nb_ff);
}

// round 5
// speedup vs baseline: 1.3299x; 1.3299x over previous
#include <cuda_runtime.h>
#include <cuda_bf16.h>
#include <cstdint>
#include <math.h>

#define IN_DIM 128
#define HID    32
#define NCLS   30
#define CP     32            // padded row width (128B fp32 rows)
#define NMAX   100000
#define EMAX   3200000
#define G2MAX  1024          // gather2 grid size (fixed)
#define PARTM  32768
#define REG_C  0.01

// ---------------- static scratch ----------------
__device__ float  d_g1 [NMAX * CP];     // g1 = (x@W1)*dinv (raw, then scaled)
__device__ float  d_g2 [NMAX * CP];     // g2 = (h1@W2)*dinv
__device__ __nv_bfloat162 d_fx16[NMAX * 16];  // FX rows, bf16, 64B/node
__device__ int    d_cnt [NMAX + 1];
__device__ int    d_cur [NMAX];
__device__ int    d_rp  [NMAX + 1];
__device__ int    d_src32[EMAX];
__device__ int    d_dst32[EMAX];
__device__ int    d_csr [EMAX];
__device__ float  d_dinv[NMAX];
__device__ int    d_blocksum[1024];
__device__ float  d_partialS[32 * G2MAX];
__device__ float  d_partialM[PARTM];
__device__ int    d_is64;

// ---------------- init + dtype detect -------------------------------------
__global__ void init_k(const unsigned int* __restrict__ w, int N) {
    int i = blockIdx.x * blockDim.x + threadIdx.x;
    if (i <= N) d_cnt[i] = 0;
    if (blockIdx.x == 0 && threadIdx.x < 64) {
        unsigned int v = w[2 * threadIdx.x + 1];     // hi-words if int64
        unsigned int any = __ballot_sync(0xffffffffu, v != 0);
        if (threadIdx.x == 0) d_is64 = (any == 0) ? 1 : 0;
    }
}

// ---------------- count + int32 conversion --------------------------------
__global__ void count_convert(const void* __restrict__ ei, int E) {
    int e = blockIdx.x * blockDim.x + threadIdx.x;
    if (e >= E) return;
    int s, d;
    if (d_is64) {
        const long long* p = (const long long*)ei;
        s = (int)p[e]; d = (int)p[(size_t)E + e];
    } else {
        const int* p = (const int*)ei;
        s = p[e]; d = p[(size_t)E + e];
    }
    d_src32[e] = s; d_dst32[e] = d;
    atomicAdd(&d_cnt[d], 1);
}

__global__ void dinv_k(int N) {
    int i = blockIdx.x * blockDim.x + threadIdx.x;
    if (i < N) d_dinv[i] = rsqrtf((float)(d_cnt[i] + 1));   // +1 self loop
}

// ---------------- 3-phase exclusive scan ----------------------------------
__global__ void scan1(int N) {
    __shared__ int sh[1024];
    int gid = blockIdx.x * 1024 + threadIdx.x;
    int v = (gid < N) ? d_cnt[gid] : 0;
    sh[threadIdx.x] = v; __syncthreads();
    for (int off = 1; off < 1024; off <<= 1) {
        int t = (threadIdx.x >= off) ? sh[threadIdx.x - off] : 0;
        __syncthreads();
        sh[threadIdx.x] += t;
        __syncthreads();
    }
    int incl = sh[threadIdx.x];
    if (gid < N) d_cur[gid] = incl - v;
    if (threadIdx.x == 1023) d_blocksum[blockIdx.x] = incl;
}

__global__ void scan2(int nb) {
    __shared__ int sh[1024];
    int v = (threadIdx.x < nb) ? d_blocksum[threadIdx.x] : 0;
    sh[threadIdx.x] = v; __syncthreads();
    for (int off = 1; off < 1024; off <<= 1) {
        int t = (threadIdx.x >= off) ? sh[threadIdx.x - off] : 0;
        __syncthreads();
        sh[threadIdx.x] += t;
        __syncthreads();
    }
    if (threadIdx.x < nb) d_blocksum[threadIdx.x] = sh[threadIdx.x] - v;
}

__global__ void scan3(int N, int E) {
    int gid = blockIdx.x * 1024 + threadIdx.x;
    if (gid < N) {
        int rp = d_cur[gid] + d_blocksum[blockIdx.x];
        d_rp[gid] = rp;
        d_cur[gid] = rp;
    }
    if (gid == 0) d_rp[N] = E;
}

// ---------------- CSR fill -------------------------------------------------
__global__ void fill_k(int E) {
    int e = blockIdx.x * blockDim.x + threadIdx.x;
    if (e >= E) return;
    int d = d_dst32[e];
    int pos = atomicAdd(&d_cur[d], 1);
    d_csr[pos] = d_src32[e];
}

// ---------------- GEMM1 (raw): g1 = x @ W1 -> d_g1 (overlapped stream) -----
__global__ void gemm1_raw(const float* __restrict__ x, const float* __restrict__ W1, int N) {
    __shared__ float Ws[IN_DIM * HID];
    for (int i = threadIdx.x; i < IN_DIM * HID; i += blockDim.x) Ws[i] = W1[i];
    __syncthreads();
    int r = blockIdx.x * blockDim.x + threadIdx.x;
    if (r >= N) return;

    float acc[HID];
#pragma unroll
    for (int c = 0; c < HID; c++) acc[c] = 0.f;

    const float4* x4 = reinterpret_cast<const float4*>(x + (size_t)r * IN_DIM);
#pragma unroll 4
    for (int k4 = 0; k4 < IN_DIM / 4; k4++) {
        float4 xv = x4[k4];
        int k = k4 * 4;
#pragma unroll
        for (int c = 0; c < HID; c++) {
            acc[c] += xv.x * Ws[(k + 0) * HID + c]
                    + xv.y * Ws[(k + 1) * HID + c]
                    + xv.z * Ws[(k + 2) * HID + c]
                    + xv.w * Ws[(k + 3) * HID + c];
        }
    }
    float* out = d_g1 + (size_t)r * CP;
#pragma unroll
    for (int c = 0; c < HID; c++) out[c] = acc[c];
}

// ---------------- scale g1 by dinv (join point) ----------------------------
__global__ void scaleg1(int N) {
    int i = blockIdx.x * blockDim.x + threadIdx.x;   // one float4 each
    int n4 = N * CP / 4;
    if (i >= n4) return;
    float s = d_dinv[i >> 3];
    float4* p = reinterpret_cast<float4*>(d_g1) + i;
    float4 v = *p;
    v.x *= s; v.y *= s; v.z *= s; v.w *= s;
    *p = v;
}

// ---- gather layer1 fused with GEMM2: d_g2 = dinv*(relu(...)@W2) -----------
__global__ void gather1(const float* __restrict__ b1, const float* __restrict__ W2, int N) {
    __shared__ float Ws[HID * CP];
    for (int i = threadIdx.x; i < HID * CP; i += blockDim.x) {
        int k = i / CP, c = i % CP;
        Ws[i] = (c < NCLS) ? W2[k * NCLS + c] : 0.f;
    }
    __syncthreads();

    int tid  = threadIdx.x;
    int lane = tid & 31;
    int warp = (blockIdx.x * blockDim.x + tid) >> 5;
    int nwarps = (gridDim.x * blockDim.x) >> 5;
    float bv = b1[lane];

    for (int v = warp; v < N; v += nwarps) {
        int e = d_rp[v], end = d_rp[v + 1];
        int n = end - e;
        float acc = 0.f;
        int s0 = 0, s1 = 0, s2 = 0, s3 = 0;
        if (n >= 4) { s0 = d_csr[e]; s1 = d_csr[e+1]; s2 = d_csr[e+2]; s3 = d_csr[e+3]; }
        while (n >= 4) {
            int t0 = 0, t1 = 0, t2 = 0, t3 = 0;
            if (n >= 8) { t0 = d_csr[e+4]; t1 = d_csr[e+5]; t2 = d_csr[e+6]; t3 = d_csr[e+7]; }
            float a0 = d_g1[(size_t)s0 * CP + lane];
            float a1 = d_g1[(size_t)s1 * CP + lane];
            float a2 = d_g1[(size_t)s2 * CP + lane];
            float a3 = d_g1[(size_t)s3 * CP + lane];
            acc += (a0 + a1) + (a2 + a3);
            s0 = t0; s1 = t1; s2 = t2; s3 = t3;
            e += 4; n -= 4;
        }
        for (; n > 0; n--, e++) acc += d_g1[(size_t)d_csr[e] * CP + lane];

        float dv = d_dinv[v];
        float h = fmaxf(dv * (acc + d_g1[(size_t)v * CP + lane]) + bv, 0.f);

        // fused GEMM2: g2[c] = dv * sum_k h[k] * W2[k][c]
        float g2c = 0.f;
#pragma unroll
        for (int k = 0; k < HID; k++) {
            float hk = __shfl_sync(0xffffffffu, h, k);
            g2c += hk * Ws[k * CP + lane];
        }
        d_g2[(size_t)v * CP + lane] = dv * g2c;
    }
}

// ---- gather layer2 + softmax + FX out + bf16 copy + NFX partials ----------
__global__ void gather2(const float* __restrict__ b2, float* __restrict__ fx_out, int N) {
    __shared__ float Ss[32];
    int tid  = threadIdx.x;
    int lane = tid & 31;
    if (tid < 32) Ss[tid] = 0.f;
    __syncthreads();

    int warp = (blockIdx.x * blockDim.x + tid) >> 5;
    int nwarps = (gridDim.x * blockDim.x) >> 5;
    float bv = (lane < NCLS) ? b2[lane] : 0.f;
    float ls = 0.f;

    for (int v = warp; v < N; v += nwarps) {
        int e = d_rp[v], end = d_rp[v + 1];
        int n = end - e;
        float acc = 0.f;
        int s0 = 0, s1 = 0, s2 = 0, s3 = 0;
        if (n >= 4) { s0 = d_csr[e]; s1 = d_csr[e+1]; s2 = d_csr[e+2]; s3 = d_csr[e+3]; }
        while (n >= 4) {
            int t0 = 0, t1 = 0, t2 = 0, t3 = 0;
            if (n >= 8) { t0 = d_csr[e+4]; t1 = d_csr[e+5]; t2 = d_csr[e+6]; t3 = d_csr[e+7]; }
            float a0 = d_g2[(size_t)s0 * CP + lane];
            float a1 = d_g2[(size_t)s1 * CP + lane];
            float a2 = d_g2[(size_t)s2 * CP + lane];
            float a3 = d_g2[(size_t)s3 * CP + lane];
            acc += (a0 + a1) + (a2 + a3);
            s0 = t0; s1 = t1; s2 = t2; s3 = t3;
            e += 4; n -= 4;
        }
        for (; n > 0; n--, e++) acc += d_g2[(size_t)d_csr[e] * CP + lane];

        float logit = d_dinv[v] * (acc + d_g2[(size_t)v * CP + lane]) + bv;
        if (lane >= NCLS) logit = -1e30f;

        float mx = logit;
#pragma unroll
        for (int o = 16; o; o >>= 1) mx = fmaxf(mx, __shfl_xor_sync(0xffffffffu, mx, o));
        float ex = expf(logit - mx);
        float sum = ex;
#pragma unroll
        for (int o = 16; o; o >>= 1) sum += __shfl_xor_sync(0xffffffffu, sum, o);
        float fx = ex / sum;                       // 0 for lane>=NCLS

        // bf16 packed copy for FF
        float fx_hi = __shfl_down_sync(0xffffffffu, fx, 1);
        if ((lane & 1) == 0)
            d_fx16[(size_t)v * 16 + (lane >> 1)] = __floats2bfloat162_rn(fx, fx_hi);

        if (lane < NCLS) {
            fx_out[(size_t)v * NCLS + lane] = fx;
            ls += log1pf(-fx * fx);
        }
    }
    atomicAdd(&Ss[lane], ls);
    __syncthreads();
    if (tid < NCLS) d_partialS[tid * gridDim.x + blockIdx.x] = Ss[tid];
}

// ---------------- FF + MSE partials (bf16 rows, 4 lanes/edge) --------------
__global__ void ff_k(const float* __restrict__ ep, int E) {
    __shared__ float sAcc;
    int tid = threadIdx.x;
    if (tid == 0) sAcc = 0.f;
    __syncthreads();

    int idx = blockIdx.x * blockDim.x + tid;
    int e = idx >> 2, c = idx & 3;
    bool valid = (e < E);

    float acc = 0.f;
    if (valid) {
        int s = d_src32[e];
        int d = d_dst32[e];
        const uint4* rs = reinterpret_cast<const uint4*>(d_fx16 + (size_t)s * 16);
        const uint4* rd = reinterpret_cast<const uint4*>(d_fx16 + (size_t)d * 16);
        uint4 A = rs[c], B = rd[c];
        const unsigned int aw[4] = {A.x, A.y, A.z, A.w};
        const unsigned int bw[4] = {B.x, B.y, B.z, B.w};
#pragma unroll
        for (int j = 0; j < 4; j++) {
            float2 af = __bfloat1622float2(*reinterpret_cast<const __nv_bfloat162*>(&aw[j]));
            float2 bf = __bfloat1622float2(*reinterpret_cast<const __nv_bfloat162*>(&bw[j]));
            acc += af.x * bf.x + af.y * bf.y;
        }
    }
    acc += __shfl_down_sync(0xffffffffu, acc, 1);
    acc += __shfl_down_sync(0xffffffffu, acc, 2);

    float d2 = 0.f;
    if (valid && c == 0) {
        float diff = acc - ep[e];
        d2 = diff * diff;
    }
    d2 += __shfl_down_sync(0xffffffffu, d2, 4);
    d2 += __shfl_down_sync(0xffffffffu, d2, 8);
    d2 += __shfl_down_sync(0xffffffffu, d2, 16);
    if ((tid & 31) == 0) atomicAdd(&sAcc, d2);
    __syncthreads();
    if (tid == 0) d_partialM[blockIdx.x] = sAcc;
}

// ---------------- finalize loss -------------------------------------------
__global__ void fin_k(float* __restrict__ out, int N, int E, int out_size, int nb_m) {
    __shared__ double sS[32];
    __shared__ double red[32];
    int tid = threadIdx.x, w = tid >> 5, lane = tid & 31;

    if (w < NCLS) {
        float s = 0.f;
        for (int k = lane; k < G2MAX; k += 32) s += d_partialS[w * G2MAX + k];
#pragma unroll
        for (int o = 16; o; o >>= 1) s += __shfl_down_sync(0xffffffffu, s, o);
        if (lane == 0) sS[w] = (double)s;
    }

    double m = 0.0;
    for (int k = tid; k < nb_m; k += 1024) m += (double)d_partialM[k];
#pragma unroll
    for (int o = 16; o; o >>= 1) m += __shfl_down_sync(0xffffffffu, m, o);
    if (lane == 0) red[w] = m;
    __syncthreads();

    if (tid == 0) {
        double mm = 0.0;
        for (int i = 0; i < 32; i++) mm += red[i];
        double preg = 0.0;
        for (int c = 0; c < NCLS; c++)
            preg -= log(1.0001 - exp(sS[c]));
        double loss = mm / (double)E + REG_C * preg;
        if (out_size > N * NCLS) out[(size_t)N * NCLS] = (float)loss;
    }
}

// ---------------- launch ---------------------------------------------------
extern "C" void kernel_launch(void* const* d_in, const int* in_sizes, int n_in,
                              void* d_out, int out_size) {
    const float* x   = (const float*)d_in[0];
    const void*  ei  = d_in[1];
    const float* ep  = (const float*)d_in[2];
    const float* W1  = (const float*)d_in[3];
    const float* b1  = (const float*)d_in[4];
    const float* W2  = (const float*)d_in[5];
    const float* b2  = (const float*)d_in[6];
    float* out = (float*)d_out;

    int N = in_sizes[0] / IN_DIM;    // 100000
    int E = in_sizes[2];             // 3200000
    int nb_scan = (N + 1023) / 1024;
    int nb_ff   = ((size_t)E * 4 + 1023) / 1024;
    int n4 = N * CP / 4;

    // one-time stream/event setup (outside capture on the correctness call)
    static cudaStream_t s_aux = nullptr;
    static cudaEvent_t ev_root = nullptr, ev_dinv = nullptr, ev_g1 = nullptr;
    if (s_aux == nullptr) {
        cudaStreamCreateWithFlags(&s_aux, cudaStreamNonBlocking);
        cudaEventCreateWithFlags(&ev_root, cudaEventDisableTiming);
        cudaEventCreateWithFlags(&ev_dinv, cudaEventDisableTiming);
        cudaEventCreateWithFlags(&ev_g1,   cudaEventDisableTiming);
    }

    const int T = 256;

    // fork: aux stream runs gemm1_raw concurrently with CSR build
    cudaEventRecord(ev_root, 0);
    cudaStreamWaitEvent(s_aux, ev_root, 0);
    gemm1_raw<<<(N + 127) / 128, 128, 0, s_aux>>>(x, W1, N);

    // main chain: CSR build
    init_k       <<<(N + 1 + T - 1) / T, T>>>((const unsigned int*)ei, N);
    count_convert<<<(E + T - 1) / T, T>>>(ei, E);
    dinv_k       <<<(N + T - 1) / T, T>>>(N);
    cudaEventRecord(ev_dinv, 0);

    // aux: scale g1 once dinv is ready
    cudaStreamWaitEvent(s_aux, ev_dinv, 0);
    scaleg1<<<(n4 + T - 1) / T, T, 0, s_aux>>>(N);
    cudaEventRecord(ev_g1, s_aux);

    scan1        <<<nb_scan, 1024>>>(N);
    scan2        <<<1, 1024>>>(nb_scan);
    scan3        <<<nb_scan, 1024>>>(N, E);
    fill_k       <<<(E + T - 1) / T, T>>>(E);

    // join, then the fused pipeline
    cudaStreamWaitEvent(0, ev_g1, 0);
    gather1      <<<2048, 256>>>(b1, W2, N);
    gather2      <<<G2MAX, 256>>>(b2, out, N);
    ff_k         <<<nb_ff, 1024>>>(ep, E);
    fin_k        <<<1, 1024>>>(out, N, E, out_size, nb_ff);
}

// round 8
// speedup vs baseline: 1.4275x; 1.0734x over previous
#include <cuda_runtime.h>
#include <cuda_bf16.h>
#include <cstdint>
#include <math.h>

#define IN_DIM 128
#define HID    32
#define NCLS   30
#define CP     32            // padded row width (128B fp32 rows)
#define NMAX   100000
#define EMAX   3200000
#define EPAD   4001024       // EMAX + 8*(NMAX+1) rounded up
#define G2MAX  2048          // gather2 grid size (fixed)
#define PARTM  32768
#define REG_C  0.01

// ---------------- static scratch ----------------
__device__ float  d_g1 [(NMAX + 1) * CP];   // g1 rows + zero sentinel row N
__device__ float  d_g2 [(NMAX + 1) * CP];   // g2 rows + zero sentinel row N
__device__ __nv_bfloat162 d_fx16[NMAX * 16];
__device__ int    d_cnt [NMAX + 1];
__device__ int    d_cur [NMAX + 1];
__device__ int    d_rp  [NMAX + 1];         // padded CSR row pointers (mult of 8)
__device__ int    d_src32[EMAX];
__device__ int    d_dst32[EMAX];
__device__ int    d_csr [EPAD];
__device__ float  d_dinv[NMAX];
__device__ int    d_blocksum[1024];
__device__ float  d_partialS[32 * G2MAX];
__device__ float  d_partialM[PARTM];
__device__ int    d_is64;

// ---------------- init: cnt=0, csr=sentinel, zero rows, dtype detect -------
__global__ void init_k(const unsigned int* __restrict__ w, int N, int Epad) {
    int i = blockIdx.x * blockDim.x + threadIdx.x;
    if (i < Epad) d_csr[i] = N;               // sentinel -> zero row
    if (i <= N)   d_cnt[i] = 0;
    if (i < CP) { d_g1[(size_t)N * CP + i] = 0.f; d_g2[(size_t)N * CP + i] = 0.f; }
    if (blockIdx.x == 0 && threadIdx.x < 64) {
        unsigned int v = w[2 * threadIdx.x + 1];
        unsigned int any = __ballot_sync(0xffffffffu, v != 0);
        if (threadIdx.x == 0) d_is64 = (any == 0) ? 1 : 0;
    }
}

// ---------------- count + int32 conversion --------------------------------
__global__ void count_convert(const void* __restrict__ ei, int E) {
    int e = blockIdx.x * blockDim.x + threadIdx.x;
    if (e >= E) return;
    int s, d;
    if (d_is64) {
        const long long* p = (const long long*)ei;
        s = (int)p[e]; d = (int)p[(size_t)E + e];
    } else {
        const int* p = (const int*)ei;
        s = p[e]; d = p[(size_t)E + e];
    }
    d_src32[e] = s; d_dst32[e] = d;
    atomicAdd(&d_cnt[d], 1);
}

__global__ void dinv_k(int N) {
    int i = blockIdx.x * blockDim.x + threadIdx.x;
    if (i < N) d_dinv[i] = rsqrtf((float)(d_cnt[i] + 1));   // +1 self loop
}

// ---------------- scan over PADDED counts (N+1 elements) -------------------
__global__ void scan1(int N) {
    __shared__ int sh[1024];
    int gid = blockIdx.x * 1024 + threadIdx.x;
    int v = 0;
    if (gid <= N) v = (d_cnt[gid] + 7) & ~7;      // padded degree
    sh[threadIdx.x] = v; __syncthreads();
    for (int off = 1; off < 1024; off <<= 1) {
        int t = (threadIdx.x >= off) ? sh[threadIdx.x - off] : 0;
        __syncthreads();
        sh[threadIdx.x] += t;
        __syncthreads();
    }
    int incl = sh[threadIdx.x];
    if (gid <= N) d_cur[gid] = incl - v;          // block-local exclusive
    if (threadIdx.x == 1023) d_blocksum[blockIdx.x] = incl;
}

// scan3 with inlined block-offset computation (scan2 eliminated)
__global__ void scan3(int N) {
    __shared__ int off_sh;
    int lane = threadIdx.x & 31;
    if (threadIdx.x < 32) {
        int s = 0;
        for (int k = lane; k < blockIdx.x; k += 32) s += d_blocksum[k];
#pragma unroll
        for (int o = 16; o; o >>= 1) s += __shfl_down_sync(0xffffffffu, s, o);
        if (lane == 0) off_sh = s;
    }
    __syncthreads();
    int gid = blockIdx.x * 1024 + threadIdx.x;
    if (gid <= N) {
        int rp = d_cur[gid] + off_sh;
        d_rp[gid] = rp;
        d_cur[gid] = rp;                           // fill cursor
    }
}

// ---------------- CSR fill (sentinel tails pre-filled by init) -------------
__global__ void fill_k(int E) {
    int e = blockIdx.x * blockDim.x + threadIdx.x;
    if (e >= E) return;
    int d = d_dst32[e];
    int pos = atomicAdd(&d_cur[d], 1);
    d_csr[pos] = d_src32[e];
}

// ---------------- GEMM1 (raw): g1 = x @ W1 (aux stream) --------------------
__global__ void gemm1_raw(const float* __restrict__ x, const float* __restrict__ W1, int N) {
    __shared__ float Ws[IN_DIM * HID];
    for (int i = threadIdx.x; i < IN_DIM * HID; i += blockDim.x) Ws[i] = W1[i];
    __syncthreads();
    int r = blockIdx.x * blockDim.x + threadIdx.x;
    if (r >= N) return;

    float acc[HID];
#pragma unroll
    for (int c = 0; c < HID; c++) acc[c] = 0.f;

    const float4* x4 = reinterpret_cast<const float4*>(x + (size_t)r * IN_DIM);
#pragma unroll 4
    for (int k4 = 0; k4 < IN_DIM / 4; k4++) {
        float4 xv = x4[k4];
        int k = k4 * 4;
#pragma unroll
        for (int c = 0; c < HID; c++) {
            acc[c] += xv.x * Ws[(k + 0) * HID + c]
                    + xv.y * Ws[(k + 1) * HID + c]
                    + xv.z * Ws[(k + 2) * HID + c]
                    + xv.w * Ws[(k + 3) * HID + c];
        }
    }
    float* out = d_g1 + (size_t)r * CP;
#pragma unroll
    for (int c = 0; c < HID; c++) out[c] = acc[c];
}

// ---------------- scale g1 by dinv (join point) ----------------------------
__global__ void scaleg1(int N) {
    int i = blockIdx.x * blockDim.x + threadIdx.x;
    int n4 = N * CP / 4;
    if (i >= n4) return;
    float s = d_dinv[i >> 3];
    float4* p = reinterpret_cast<float4*>(d_g1) + i;
    float4 v = *p;
    v.x *= s; v.y *= s; v.z *= s; v.w *= s;
    *p = v;
}

// ---- gather layer1 (8-wide, sentinel-padded) fused with GEMM2 -------------
__global__ void gather1(const float* __restrict__ b1, const float* __restrict__ W2, int N) {
    __shared__ float Ws[HID * CP];
    for (int i = threadIdx.x; i < HID * CP; i += blockDim.x) {
        int k = i / CP, c = i % CP;
        Ws[i] = (c < NCLS) ? W2[k * NCLS + c] : 0.f;
    }
    __syncthreads();

    int tid  = threadIdx.x;
    int lane = tid & 31;
    int warp = (blockIdx.x * blockDim.x + tid) >> 5;
    int nwarps = (gridDim.x * blockDim.x) >> 5;
    float bv = b1[lane];

    for (int v = warp; v < N; v += nwarps) {
        int beg = d_rp[v];
        int nb  = (d_rp[v + 1] - beg) >> 3;
        const int4* ip = reinterpret_cast<const int4*>(d_csr + beg);
        float acc = 0.f;
        int4 i0, i1;
        if (nb > 0) { i0 = ip[0]; i1 = ip[1]; }
        for (int b = 0; b < nb; b++) {
            int4 n0, n1;
            if (b + 1 < nb) { n0 = ip[2 * b + 2]; n1 = ip[2 * b + 3]; }
            float a0 = d_g1[(size_t)i0.x * CP + lane];
            float a1 = d_g1[(size_t)i0.y * CP + lane];
            float a2 = d_g1[(size_t)i0.z * CP + lane];
            float a3 = d_g1[(size_t)i0.w * CP + lane];
            float a4 = d_g1[(size_t)i1.x * CP + lane];
            float a5 = d_g1[(size_t)i1.y * CP + lane];
            float a6 = d_g1[(size_t)i1.z * CP + lane];
            float a7 = d_g1[(size_t)i1.w * CP + lane];
            acc += ((a0 + a1) + (a2 + a3)) + ((a4 + a5) + (a6 + a7));
            i0 = n0; i1 = n1;
        }
        float dv = d_dinv[v];
        float h = fmaxf(dv * (acc + d_g1[(size_t)v * CP + lane]) + bv, 0.f);

        // fused GEMM2: g2[c] = dv * sum_k h[k] * W2[k][c]
        float g2c = 0.f;
#pragma unroll
        for (int k = 0; k < HID; k++) {
            float hk = __shfl_sync(0xffffffffu, h, k);
            g2c += hk * Ws[k * CP + lane];
        }
        d_g2[(size_t)v * CP + lane] = dv * g2c;
    }
}

// ---- gather layer2 (8-wide) + softmax + FX + bf16 copy + NFX partials -----
__global__ void gather2(const float* __restrict__ b2, float* __restrict__ fx_out, int N) {
    __shared__ float Ss[32];
    int tid  = threadIdx.x;
    int lane = tid & 31;
    if (tid < 32) Ss[tid] = 0.f;
    __syncthreads();

    int warp = (blockIdx.x * blockDim.x + tid) >> 5;
    int nwarps = (gridDim.x * blockDim.x) >> 5;
    float bv = (lane < NCLS) ? b2[lane] : 0.f;
    float ls = 0.f;

    for (int v = warp; v < N; v += nwarps) {
        int beg = d_rp[v];
        int nb  = (d_rp[v + 1] - beg) >> 3;
        const int4* ip = reinterpret_cast<const int4*>(d_csr + beg);
        float acc = 0.f;
        int4 i0, i1;
        if (nb > 0) { i0 = ip[0]; i1 = ip[1]; }
        for (int b = 0; b < nb; b++) {
            int4 n0, n1;
            if (b + 1 < nb) { n0 = ip[2 * b + 2]; n1 = ip[2 * b + 3]; }
            float a0 = d_g2[(size_t)i0.x * CP + lane];
            float a1 = d_g2[(size_t)i0.y * CP + lane];
            float a2 = d_g2[(size_t)i0.z * CP + lane];
            float a3 = d_g2[(size_t)i0.w * CP + lane];
            float a4 = d_g2[(size_t)i1.x * CP + lane];
            float a5 = d_g2[(size_t)i1.y * CP + lane];
            float a6 = d_g2[(size_t)i1.z * CP + lane];
            float a7 = d_g2[(size_t)i1.w * CP + lane];
            acc += ((a0 + a1) + (a2 + a3)) + ((a4 + a5) + (a6 + a7));
            i0 = n0; i1 = n1;
        }
        float logit = d_dinv[v] * (acc + d_g2[(size_t)v * CP + lane]) + bv;
        if (lane >= NCLS) logit = -1e30f;

        float mx = logit;
#pragma unroll
        for (int o = 16; o; o >>= 1) mx = fmaxf(mx, __shfl_xor_sync(0xffffffffu, mx, o));
        float ex = expf(logit - mx);
        float sum = ex;
#pragma unroll
        for (int o = 16; o; o >>= 1) sum += __shfl_xor_sync(0xffffffffu, sum, o);
        float fx = ex / sum;                       // 0 for lane>=NCLS

        float fx_hi = __shfl_down_sync(0xffffffffu, fx, 1);
        if ((lane & 1) == 0)
            d_fx16[(size_t)v * 16 + (lane >> 1)] = __floats2bfloat162_rn(fx, fx_hi);

        if (lane < NCLS) {
            fx_out[(size_t)v * NCLS + lane] = fx;
            ls += log1pf(-fx * fx);
        }
    }
    atomicAdd(&Ss[lane], ls);
    __syncthreads();
    if (tid < NCLS) d_partialS[tid * gridDim.x + blockIdx.x] = Ss[tid];
}

// ---------------- FF + MSE partials (2 edges per 4-lane group) -------------
// All shuffles execute unconditionally on every lane (no divergent sync).
__global__ void ff_k(const float* __restrict__ ep, int E) {
    __shared__ float sAcc;
    int tid = threadIdx.x;
    if (tid == 0) sAcc = 0.f;
    __syncthreads();

    int idx = blockIdx.x * blockDim.x + tid;
    int grp = idx >> 2, c = idx & 3;
    int e0 = grp * 2;
    int nGrp = (E + 1) >> 1;
    bool v0 = (grp < nGrp) && (e0 < E);
    bool v1 = (grp < nGrp) && (e0 + 1 < E);

    float p0 = 0.f, p1 = 0.f;
    if (v0) {
        int s0 = d_src32[e0], dd0 = d_dst32[e0];
        uint4 A0 = reinterpret_cast<const uint4*>(d_fx16 + (size_t)s0  * 16)[c];
        uint4 B0 = reinterpret_cast<const uint4*>(d_fx16 + (size_t)dd0 * 16)[c];
        const unsigned int aw[4] = {A0.x, A0.y, A0.z, A0.w};
        const unsigned int bw[4] = {B0.x, B0.y, B0.z, B0.w};
#pragma unroll
        for (int j = 0; j < 4; j++) {
            float2 af = __bfloat1622float2(*reinterpret_cast<const __nv_bfloat162*>(&aw[j]));
            float2 bf = __bfloat1622float2(*reinterpret_cast<const __nv_bfloat162*>(&bw[j]));
            p0 += af.x * bf.x + af.y * bf.y;
        }
    }
    if (v1) {
        int s1 = d_src32[e0 + 1], dd1 = d_dst32[e0 + 1];
        uint4 A1 = reinterpret_cast<const uint4*>(d_fx16 + (size_t)s1  * 16)[c];
        uint4 B1 = reinterpret_cast<const uint4*>(d_fx16 + (size_t)dd1 * 16)[c];
        const unsigned int aw[4] = {A1.x, A1.y, A1.z, A1.w};
        const unsigned int bw[4] = {B1.x, B1.y, B1.z, B1.w};
#pragma unroll
        for (int j = 0; j < 4; j++) {
            float2 af = __bfloat1622float2(*reinterpret_cast<const __nv_bfloat162*>(&aw[j]));
            float2 bf = __bfloat1622float2(*reinterpret_cast<const __nv_bfloat162*>(&bw[j]));
            p1 += af.x * bf.x + af.y * bf.y;
        }
    }

    // uniform shuffles: reduce 4-lane partial dots
    p0 += __shfl_down_sync(0xffffffffu, p0, 1);
    p0 += __shfl_down_sync(0xffffffffu, p0, 2);
    p1 += __shfl_down_sync(0xffffffffu, p1, 1);
    p1 += __shfl_down_sync(0xffffffffu, p1, 2);

    float d2 = 0.f;
    if (c == 0) {
        if (v0) { float f = p0 - ep[e0];     d2 += f * f; }
        if (v1) { float f = p1 - ep[e0 + 1]; d2 += f * f; }
    }
    d2 += __shfl_down_sync(0xffffffffu, d2, 4);
    d2 += __shfl_down_sync(0xffffffffu, d2, 8);
    d2 += __shfl_down_sync(0xffffffffu, d2, 16);
    if ((tid & 31) == 0) atomicAdd(&sAcc, d2);
    __syncthreads();
    if (tid == 0) d_partialM[blockIdx.x] = sAcc;
}

// ---------------- finalize loss -------------------------------------------
__global__ void fin_k(float* __restrict__ out, int N, int E, int out_size, int nb_m) {
    __shared__ double sS[32];
    __shared__ double red[32];
    int tid = threadIdx.x, w = tid >> 5, lane = tid & 31;

    if (w < NCLS) {
        float s = 0.f;
        for (int k = lane; k < G2MAX; k += 32) s += d_partialS[w * G2MAX + k];
#pragma unroll
        for (int o = 16; o; o >>= 1) s += __shfl_down_sync(0xffffffffu, s, o);
        if (lane == 0) sS[w] = (double)s;
    }

    double m = 0.0;
    for (int k = tid; k < nb_m; k += 1024) m += (double)d_partialM[k];
#pragma unroll
    for (int o = 16; o; o >>= 1) m += __shfl_down_sync(0xffffffffu, m, o);
    if (lane == 0) red[w] = m;
    __syncthreads();

    if (tid == 0) {
        double mm = 0.0;
        for (int i = 0; i < 32; i++) mm += red[i];
        double preg = 0.0;
        for (int c = 0; c < NCLS; c++)
            preg -= log(1.0001 - exp(sS[c]));
        double loss = mm / (double)E + REG_C * preg;
        if (out_size > N * NCLS) out[(size_t)N * NCLS] = (float)loss;
    }
}

// ---------------- launch ---------------------------------------------------
extern "C" void kernel_launch(void* const* d_in, const int* in_sizes, int n_in,
                              void* d_out, int out_size) {
    const float* x   = (const float*)d_in[0];
    const void*  ei  = d_in[1];
    const float* ep  = (const float*)d_in[2];
    const float* W1  = (const float*)d_in[3];
    const float* b1  = (const float*)d_in[4];
    const float* W2  = (const float*)d_in[5];
    const float* b2  = (const float*)d_in[6];
    float* out = (float*)d_out;

    int N = in_sizes[0] / IN_DIM;    // 100000
    int E = in_sizes[2];             // 3200000
    int nb_scan = (N + 1 + 1023) / 1024;
    long long ff_threads = ((long long)E + 1) / 2 * 4;
    int nb_ff   = (int)((ff_threads + 1023) / 1024);
    int n4 = N * CP / 4;
    int Epad = EPAD;

    static cudaStream_t s_aux = nullptr;
    static cudaEvent_t ev_root = nullptr, ev_dinv = nullptr, ev_g1 = nullptr;
    if (s_aux == nullptr) {
        cudaStreamCreateWithFlags(&s_aux, cudaStreamNonBlocking);
        cudaEventCreateWithFlags(&ev_root, cudaEventDisableTiming);
        cudaEventCreateWithFlags(&ev_dinv, cudaEventDisableTiming);
        cudaEventCreateWithFlags(&ev_g1,   cudaEventDisableTiming);
    }

    const int T = 256;

    // fork: aux stream runs gemm1_raw concurrently with CSR build
    cudaEventRecord(ev_root, 0);
    cudaStreamWaitEvent(s_aux, ev_root, 0);
    gemm1_raw<<<(N + 127) / 128, 128, 0, s_aux>>>(x, W1, N);

    // main chain: CSR build
    init_k       <<<(Epad + T - 1) / T, T>>>((const unsigned int*)ei, N, Epad);
    count_convert<<<(E + T - 1) / T, T>>>(ei, E);
    dinv_k       <<<(N + T - 1) / T, T>>>(N);
    cudaEventRecord(ev_dinv, 0);

    cudaStreamWaitEvent(s_aux, ev_dinv, 0);
    scaleg1<<<(n4 + T - 1) / T, T, 0, s_aux>>>(N);
    cudaEventRecord(ev_g1, s_aux);

    scan1        <<<nb_scan, 1024>>>(N);
    scan3        <<<nb_scan, 1024>>>(N);
    fill_k       <<<(E + T - 1) / T, T>>>(E);

    cudaStreamWaitEvent(0, ev_g1, 0);
    gather1      <<<2048, 256>>>(b1, W2, N);
    gather2      <<<G2MAX, 256>>>(b2, out, N);
    ff_k         <<<nb_ff, 1024>>>(ep, E);
    fin_k        <<<1, 1024>>>(out, N, E, out_size, nb_ff);
}